// round 3
// baseline (speedup 1.0000x reference)
#include <cuda_runtime.h>
#include <math.h>

// HopAttentionLayer: B=256, T=64, N=2048, D=128
// attention[b,n] = softmax_n( T * <context[b,n,:], W[D:2D]> )
//   (tgt_term and bias are constant over n -> drop out of softmax)
// out[b,n,d] = attention[b,n] * context[b,n,d]

#define BDIM 512
static constexpr int Bsz  = 256;
static constexpr int Nctx = 2048;
static constexpr int Dd   = 128;
static constexpr int NWARP = BDIM / 32;            // 16
static constexpr int ROWS_PER_WARP = Nctx / NWARP; // 128
static constexpr int VPT = Nctx / BDIM;            // 4 scores per thread

__global__ __launch_bounds__(BDIM)
void hop_attn_kernel(const float* __restrict__ ctx,
                     const float* __restrict__ W,
                     float* __restrict__ out)
{
    __shared__ float s_att[Nctx];   // scores -> probs
    __shared__ float s_red[NWARP];

    const int b    = blockIdx.x;
    const int tid  = threadIdx.x;
    const int warp = tid >> 5;
    const int lane = tid & 31;

    // Wc slice for this lane (W[128 + lane*4 .. +3])
    const float4 wc = *reinterpret_cast<const float4*>(W + Dd + lane * 4);

    const float*  cbase = ctx + (size_t)b * Nctx * Dd;
    const float4* c4    = reinterpret_cast<const float4*>(cbase);
    float4*       o4    = reinterpret_cast<float4*>(out) + (size_t)b * (Nctx * Dd / 4);

    // ---- Pass 1: ctx_term dot products (warp per row, float4 per lane) ----
    // Interleaved rows: at step k the CTA reads rows [k*16, k*16+16) — one
    // contiguous 8KB window, good DRAM/L2 locality.
    #pragma unroll 4
    for (int k = 0; k < ROWS_PER_WARP; k++) {
        const int row = k * NWARP + warp;
        float4 v = *reinterpret_cast<const float4*>(cbase + row * Dd + lane * 4);
        float d = v.x * wc.x + v.y * wc.y + v.z * wc.z + v.w * wc.w;
        #pragma unroll
        for (int o = 16; o; o >>= 1) d += __shfl_xor_sync(0xffffffffu, d, o);
        if (lane == 0) s_att[row] = 64.0f * d;   // fold T=64
    }
    __syncthreads();

    // ---- Block max ----
    float m = -INFINITY;
    #pragma unroll
    for (int k = 0; k < VPT; k++) m = fmaxf(m, s_att[tid + k * BDIM]);
    #pragma unroll
    for (int o = 16; o; o >>= 1) m = fmaxf(m, __shfl_xor_sync(0xffffffffu, m, o));
    if (lane == 0) s_red[warp] = m;
    __syncthreads();
    {
        float mm = (tid < NWARP) ? s_red[tid] : -INFINITY;
        if (tid < 32) {
            #pragma unroll
            for (int o = 16; o; o >>= 1) mm = fmaxf(mm, __shfl_xor_sync(0xffffffffu, mm, o));
            if (tid == 0) s_red[0] = mm;
        }
    }
    __syncthreads();
    m = s_red[0];
    __syncthreads();   // everyone has read s_red[0] before it's overwritten below

    // ---- exp + block sum ----
    float e[VPT];
    float sum = 0.0f;
    #pragma unroll
    for (int k = 0; k < VPT; k++) {
        e[k] = __expf(s_att[tid + k * BDIM] - m);
        sum += e[k];
    }
    #pragma unroll
    for (int o = 16; o; o >>= 1) sum += __shfl_xor_sync(0xffffffffu, sum, o);
    if (lane == 0) s_red[warp] = sum;
    __syncthreads();
    {
        float ss = (tid < NWARP) ? s_red[tid] : 0.0f;
        if (tid < 32) {
            #pragma unroll
            for (int o = 16; o; o >>= 1) ss += __shfl_xor_sync(0xffffffffu, ss, o);
            if (tid == 0) s_red[0] = ss;
        }
    }
    __syncthreads();
    const float inv = 1.0f / s_red[0];

    #pragma unroll
    for (int k = 0; k < VPT; k++) s_att[tid + k * BDIM] = e[k] * inv;
    __syncthreads();

    // ---- Pass 2: out = attention[n] * context (float4 streaming) ----
    constexpr int NV4 = Nctx * Dd / 4;   // 65536
    #pragma unroll 4
    for (int i = 0; i < NV4 / BDIM; i++) {
        const int idx = i * BDIM + tid;
        const float a = s_att[idx >> 5];      // 32 float4 per row -> uniform per warp
        float4 v = c4[idx];
        v.x *= a; v.y *= a; v.z *= a; v.w *= a;
        o4[idx] = v;
    }
}

extern "C" void kernel_launch(void* const* d_in, const int* in_sizes, int n_in,
                              void* d_out, int out_size)
{
    // d_in[0]=targetsentence_emb (unused), d_in[1]=context_emb, d_in[2]=W, d_in[3]=b (unused)
    const float* ctx = (const float*)d_in[1];
    const float* W   = (const float*)d_in[2];
    float* out       = (float*)d_out;
    hop_attn_kernel<<<Bsz, BDIM>>>(ctx, W, out);
}

// round 4
// speedup vs baseline: 1.0981x; 1.0981x over previous
#include <cuda_runtime.h>
#include <math.h>
#include <stdint.h>

// HopAttentionLayer: B=256, T=64, N=2048, D=128
// attention[b,n] = softmax_n( 64 * <context[b,n,:], W[128:256]> )
// out[b,n,d] = attention[b,n] * context[b,n,d]
//
// Cluster-of-8 decomposition: each CTA owns 256 rows (128 KB). Read once for
// scores, exchange softmax stats via DSMEM, re-read from L2 (short reuse
// distance), write. DRAM traffic = read-once + write-once = 536 MB floor.

#define BDIM 512
static constexpr int Bsz  = 256;
static constexpr int Nctx = 2048;
static constexpr int Dd   = 128;
static constexpr int CS   = 8;            // cluster size (CTAs per batch)
static constexpr int RS   = Nctx / CS;    // 256 rows per CTA
static constexpr int NWARP = BDIM / 32;   // 16

__device__ __forceinline__ uint32_t smem_u32(const void* p) {
    uint32_t a;
    asm("{ .reg .u64 t; cvta.to.shared.u64 t, %1; cvt.u32.u64 %0, t; }"
        : "=r"(a) : "l"(p));
    return a;
}
__device__ __forceinline__ float dsmem_ld_f32(uint32_t laddr, uint32_t rank) {
    uint32_t ra;
    asm("mapa.shared::cluster.u32 %0, %1, %2;" : "=r"(ra) : "r"(laddr), "r"(rank));
    float v;
    asm volatile("ld.shared::cluster.f32 %0, [%1];" : "=f"(v) : "r"(ra));
    return v;
}
#define CLUSTER_SYNC() do { \
    asm volatile("barrier.cluster.arrive.aligned;" ::: "memory"); \
    asm volatile("barrier.cluster.wait.aligned;"   ::: "memory"); \
} while (0)

__global__ __launch_bounds__(BDIM) __cluster_dims__(CS, 1, 1)
void hop_attn_cluster(const float* __restrict__ ctx,
                      const float* __restrict__ W,
                      float* __restrict__ out)
{
    __shared__ float s_score[RS];     // scores -> probs for this slice
    __shared__ float s_red[NWARP];
    __shared__ float s_pub[2];        // published to cluster: [0]=lmax [1]=lsum
    __shared__ float s_glb[2];        // gathered:             [0]=gmax [1]=gsum

    const int rank  = blockIdx.x;     // slice within batch (== cluster ctarank)
    const int batch = blockIdx.y;
    const int tid   = threadIdx.x;
    const int warp  = tid >> 5;
    const int lane  = tid & 31;

    const float4 wc = *reinterpret_cast<const float4*>(W + Dd + lane * 4);

    const float4* c4 = reinterpret_cast<const float4*>(ctx)
                     + ((size_t)batch * Nctx + rank * RS) * (Dd / 4);
    float4*       o4 = reinterpret_cast<float4*>(out)
                     + ((size_t)batch * Nctx + rank * RS) * (Dd / 4);

    // ---- Pass 1: dot products, warp per row (16 warps x 16 steps = 256 rows) ----
    #pragma unroll
    for (int k = 0; k < RS / NWARP; k++) {
        const int row = k * NWARP + warp;           // contiguous 8KB window per step
        float4 v = c4[row * (Dd / 4) + lane];
        float d = v.x * wc.x + v.y * wc.y + v.z * wc.z + v.w * wc.w;
        #pragma unroll
        for (int o = 16; o; o >>= 1) d += __shfl_xor_sync(0xffffffffu, d, o);
        if (lane == 0) s_score[row] = 64.0f * d;    // fold T=64
    }
    __syncthreads();

    // ---- Local max (warps 8..15 contribute -inf) ----
    float m = (tid < RS) ? s_score[tid] : -INFINITY;
    #pragma unroll
    for (int o = 16; o; o >>= 1) m = fmaxf(m, __shfl_xor_sync(0xffffffffu, m, o));
    if (lane == 0) s_red[warp] = m;
    __syncthreads();
    if (warp == 0) {
        float mm = (lane < NWARP) ? s_red[lane] : -INFINITY;
        #pragma unroll
        for (int o = 8; o; o >>= 1) mm = fmaxf(mm, __shfl_xor_sync(0xffffffffu, mm, o));
        if (lane == 0) s_pub[0] = mm;
    }
    CLUSTER_SYNC();

    // ---- Gather global max over 8 ranks (warp 0 only, then broadcast) ----
    if (warp == 0) {
        uint32_t a = smem_u32(&s_pub[0]);
        float g = (lane < CS) ? dsmem_ld_f32(a, lane) : -INFINITY;
        #pragma unroll
        for (int o = 4; o; o >>= 1) g = fmaxf(g, __shfl_xor_sync(0xffffffffu, g, o));
        if (lane == 0) s_glb[0] = g;
    }
    __syncthreads();
    const float gmax = s_glb[0];

    // ---- exp + local sum ----
    float e = 0.0f;
    if (tid < RS) { e = __expf(s_score[tid] - gmax); s_score[tid] = e; }
    float sum = e;
    #pragma unroll
    for (int o = 16; o; o >>= 1) sum += __shfl_xor_sync(0xffffffffu, sum, o);
    if (lane == 0) s_red[warp] = sum;
    __syncthreads();
    if (warp == 0) {
        float ss = (lane < NWARP) ? s_red[lane] : 0.0f;
        #pragma unroll
        for (int o = 8; o; o >>= 1) ss += __shfl_xor_sync(0xffffffffu, ss, o);
        if (lane == 0) s_pub[1] = ss;
    }
    CLUSTER_SYNC();

    // ---- Gather global sum ----
    if (warp == 0) {
        uint32_t a = smem_u32(&s_pub[1]);
        float g = (lane < CS) ? dsmem_ld_f32(a, lane) : 0.0f;
        #pragma unroll
        for (int o = 4; o; o >>= 1) g += __shfl_xor_sync(0xffffffffu, g, o);
        if (lane == 0) s_glb[1] = g;
    }
    __syncthreads();
    const float inv = 1.0f / s_glb[1];
    if (tid < RS) s_score[tid] *= inv;
    __syncthreads();

    // ---- Pass 2: scale + write (re-read hits L2: 128KB slice, short reuse dist) ----
    constexpr int NV4 = RS * (Dd / 4);   // 8192 float4
    #pragma unroll 4
    for (int i = 0; i < NV4 / BDIM; i++) {
        const int idx = i * BDIM + tid;
        const float a = s_score[idx >> 5];   // 32 float4 per row -> uniform per warp
        float4 v = c4[idx];
        v.x *= a; v.y *= a; v.z *= a; v.w *= a;
        o4[idx] = v;
    }

    // No CTA may exit while peers could still read its SMEM (the stat reads
    // happened right after the last cluster sync; be safe).
    CLUSTER_SYNC();
}

extern "C" void kernel_launch(void* const* d_in, const int* in_sizes, int n_in,
                              void* d_out, int out_size)
{
    // d_in[0]=targetsentence_emb (unused), d_in[1]=context_emb, d_in[2]=W, d_in[3]=b (unused)
    const float* ctx = (const float*)d_in[1];
    const float* W   = (const float*)d_in[2];
    float* out       = (float*)d_out;
    hop_attn_cluster<<<dim3(CS, Bsz, 1), BDIM>>>(ctx, W, out);
}